// round 7
// baseline (speedup 1.0000x reference)
#include <cuda_runtime.h>
#include <cstdint>

#define NN   100000
#define FIN  512
#define H1   8
#define D1   64      // H1*C1
#define C2   10
#define EMAXSZ 1700000
#define CHUNK 98     // ceil((NN+1)/1024)

// ---------------- scratch (no allocs allowed) ----------------
__device__ float g_h1 [NN * D1];     // layer1 features   25.6 MB
__device__ float g_al1[NN * H1];
__device__ float g_ar1[NN * H1];
__device__ float g_z2 [NN * C2];
__device__ float g_al2[NN];
__device__ float g_ar2[NN];
// sorted-by-dst edge structures
__device__ int   g_cnt [NN];         // zero at entry (module-load init / self-restored)
__device__ int   g_off [NN + 1];
__device__ int   g_pos [NN];
__device__ int   g_esrc[EMAXSZ];

// ---------------- helpers ----------------
__device__ __forceinline__ float lrelu(float x) { return x > 0.f ? x : 0.2f * x; }

__device__ __forceinline__ float fast_exp(float x) {
    float t = x * 1.4426950408889634f;
    t = fminf(fmaxf(t, -126.f), 126.f);
    float fi = floorf(t);
    float f  = t - fi;
    int   i  = (int)fi;
    float p = 1.5403530e-4f;
    p = fmaf(p, f, 1.3333558e-3f);
    p = fmaf(p, f, 9.6181291e-3f);
    p = fmaf(p, f, 5.5504109e-2f);
    p = fmaf(p, f, 2.4022651e-1f);
    p = fmaf(p, f, 6.9314718e-1f);
    p = fmaf(p, f, 1.0f);
    return __uint_as_float(__float_as_uint(p) + ((unsigned)i << 23));
}

__device__ __forceinline__ float elu1(float x) {
    return x > 0.f ? x : fast_exp(fmaxf(x, -80.f)) - 1.f;
}

// packed fp32x2 FMA (Blackwell base ISA)
__device__ __forceinline__ unsigned long long rep2(float v) {
    unsigned long long r;
    asm("mov.b64 %0, {%1, %1};" : "=l"(r) : "f"(v));
    return r;
}
__device__ __forceinline__ void ffma2(unsigned long long& d,
                                      unsigned long long a, unsigned long long b) {
    asm("fma.rn.f32x2 %0, %1, %2, %0;" : "+l"(d) : "l"(a), "l"(b));
}
__device__ __forceinline__ float2 unpk(unsigned long long v) {
    float lo, hi;
    asm("mov.b64 {%0, %1}, %2;" : "=f"(lo), "=f"(hi) : "l"(v));
    return make_float2(lo, hi);
}

// ---------------- sort pipeline (3 launches) ----------------
__device__ __forceinline__ bool edge_sd(const int* __restrict__ src,
                                        const int* __restrict__ dst,
                                        int e, int E, int& s, int& d) {
    if (e < E) { s = src[e]; d = dst[e]; }
    else       { s = d = e - E; }
    return (unsigned)s < NN && (unsigned)d < NN;
}

// g_cnt is zero on entry (module-load init on first call; scan_kernel re-zeroes
// it each call after consuming, so every call sees the same initial state).
__global__ void hist_kernel(const int* __restrict__ src,
                            const int* __restrict__ dst, int E) {
    int e = blockIdx.x * blockDim.x + threadIdx.x;
    if (e >= E + NN) return;
    int s, d;
    if (!edge_sd(src, dst, e, E, s, d)) return;
    atomicAdd(&g_cnt[d], 1);
}

// single-block exclusive scan over g_cnt -> g_off, g_pos; zeroes g_cnt.
__global__ void scan_kernel() {
    __shared__ int sm[1024];
    int t = threadIdx.x;
    int base = t * CHUNK;
    int run = 0;
    for (int j = 0; j < CHUNK; j++) {
        int i = base + j;
        run += (i < NN) ? g_cnt[i] : 0;
    }
    sm[t] = run;
    __syncthreads();
#pragma unroll
    for (int off = 1; off < 1024; off <<= 1) {
        int v = (t >= off) ? sm[t - off] : 0;
        __syncthreads();
        sm[t] += v;
        __syncthreads();
    }
    int pre = (t == 0) ? 0 : sm[t - 1];
    run = 0;
    for (int j = 0; j < CHUNK; j++) {
        int i = base + j;
        if (i < NN) {
            int v = g_cnt[i];
            run += v;
            g_off[i + 1] = pre + run;
            g_pos[i]     = pre + run - v;
            g_cnt[i]     = 0;               // restore for next call
        }
    }
    if (t == 0) g_off[0] = 0;
}

__global__ void scatter_kernel(const int* __restrict__ src,
                               const int* __restrict__ dst, int E) {
    int e = blockIdx.x * blockDim.x + threadIdx.x;
    if (e >= E + NN) return;
    int s, d;
    if (!edge_sd(src, dst, e, E, s, d)) return;
    int p = atomicAdd(&g_pos[d], 1);
    g_esrc[p] = s;
}

// ---------------- compute kernels ----------------
// h1 = x @ W1 + fused attention-term epilogue
__global__ void gemm1_kernel(const float* __restrict__ x, const float* __restrict__ W,
                             const float* __restrict__ a_src, const float* __restrict__ a_dst) {
    __shared__ __align__(16) float As[32][64];
    __shared__ __align__(16) float Bs[32][64];
    int t  = threadIdx.x;          // 256
    int m0 = blockIdx.x * 64;
    int tx = (t & 15) * 4;
    int ty = (t >> 4) * 4;
    int lm = t & 63;
    int lk = (t >> 6) * 4;
    int kr = t >> 4;
    int nc = (t & 15) * 4;

    unsigned long long acc[4][2];
#pragma unroll
    for (int i = 0; i < 4; i++) { acc[i][0] = 0ull; acc[i][1] = 0ull; }

    int  row = m0 + lm;
    bool rok = row < NN;
    const float4* xrow = (const float4*)(x + (size_t)(rok ? row : 0) * FIN);

    for (int k0 = 0; k0 < FIN; k0 += 32) {
#pragma unroll
        for (int rep = 0; rep < 2; rep++) {
            int kk = lk + rep * 16;
            float4 v = rok ? xrow[(k0 + kk) >> 2] : make_float4(0.f, 0.f, 0.f, 0.f);
            As[kk + 0][lm] = v.x;
            As[kk + 1][lm] = v.y;
            As[kk + 2][lm] = v.z;
            As[kk + 3][lm] = v.w;
        }
#pragma unroll
        for (int rep = 0; rep < 2; rep++) {
            float4 v = *(const float4*)(W + (size_t)(k0 + kr + rep * 16) * D1 + nc);
            *(float4*)&Bs[kr + rep * 16][nc] = v;
        }
        __syncthreads();
#pragma unroll
        for (int kk = 0; kk < 32; kk++) {
            float4 a = *(const float4*)&As[kk][ty];
            ulonglong2 bb = *(const ulonglong2*)&Bs[kk][tx];
            unsigned long long a0 = rep2(a.x), a1 = rep2(a.y),
                               a2 = rep2(a.z), a3 = rep2(a.w);
            ffma2(acc[0][0], a0, bb.x); ffma2(acc[0][1], a0, bb.y);
            ffma2(acc[1][0], a1, bb.x); ffma2(acc[1][1], a1, bb.y);
            ffma2(acc[2][0], a2, bb.x); ffma2(acc[2][1], a2, bb.y);
            ffma2(acc[3][0], a3, bb.x); ffma2(acc[3][1], a3, bb.y);
        }
        __syncthreads();
    }

    float4 as4 = *(const float4*)&a_src[tx];
    float4 ad4 = *(const float4*)&a_dst[tx];
    int h = (t & 15) >> 1;                     // head covered by my 4 columns
#pragma unroll
    for (int i = 0; i < 4; i++) {
        int r = m0 + ty + i;
        float2 u0 = unpk(acc[i][0]), u1 = unpk(acc[i][1]);
        if (r < NN)
            *(float4*)&g_h1[(size_t)r * D1 + tx] = make_float4(u0.x, u0.y, u1.x, u1.y);
        float alp = u0.x * as4.x + u0.y * as4.y + u1.x * as4.z + u1.y * as4.w;
        float arp = u0.x * ad4.x + u0.y * ad4.y + u1.x * ad4.z + u1.y * ad4.w;
        alp += __shfl_xor_sync(~0u, alp, 1);
        arp += __shfl_xor_sync(~0u, arp, 1);
        if ((t & 1) == 0 && r < NN) {
            g_al1[r * H1 + h] = alp;
            g_ar1[r * H1 + h] = arp;
        }
    }
}

// layer-1 aggregation + FUSED layer-2 node prep.
// warp per dst node: accumulate numerator+denominator in regs, then directly
// compute h2 = elu(acc/denom + b1), z2 = h2 @ W2, and layer-2 attn terms.
__global__ void agg1_kernel(const float* __restrict__ b1, const float* __restrict__ W2,
                            const float* __restrict__ as2, const float* __restrict__ ad2) {
    __shared__ float s_ex[8][256];             // [warpInBlock][edge*8+head]
    int gw = (blockIdx.x * blockDim.x + threadIdx.x) >> 5;
    int w  = (threadIdx.x >> 5);
    int lane = threadIdx.x & 31;
    if (gw >= NN) return;
    int d = gw;
    int beg = g_off[d], end = g_off[d + 1];
    float4 ar0 = *(const float4*)&g_ar1[d * H1];
    float4 ar1 = *(const float4*)&g_ar1[d * H1 + 4];
    float dsum[8];
#pragma unroll
    for (int h = 0; h < 8; h++) dsum[h] = 0.f;
    float accx = 0.f, accy = 0.f;

    for (int b = beg; b < end; b += 32) {
        int n = min(32, end - b);
        int s_my = (lane < n) ? g_esrc[b + lane] : 0;
        if (lane < n) {
            float4 a0 = *(const float4*)&g_al1[s_my * H1];
            float4 a1 = *(const float4*)&g_al1[s_my * H1 + 4];
            float ex0 = fast_exp(lrelu(a0.x + ar0.x));
            float ex1 = fast_exp(lrelu(a0.y + ar0.y));
            float ex2 = fast_exp(lrelu(a0.z + ar0.z));
            float ex3 = fast_exp(lrelu(a0.w + ar0.w));
            float ex4 = fast_exp(lrelu(a1.x + ar1.x));
            float ex5 = fast_exp(lrelu(a1.y + ar1.y));
            float ex6 = fast_exp(lrelu(a1.z + ar1.z));
            float ex7 = fast_exp(lrelu(a1.w + ar1.w));
            dsum[0] += ex0; dsum[1] += ex1; dsum[2] += ex2; dsum[3] += ex3;
            dsum[4] += ex4; dsum[5] += ex5; dsum[6] += ex6; dsum[7] += ex7;
            *(float4*)&s_ex[w][lane * 8]     = make_float4(ex0, ex1, ex2, ex3);
            *(float4*)&s_ex[w][lane * 8 + 4] = make_float4(ex4, ex5, ex6, ex7);
        }
        __syncwarp();
        for (int j = 0; j < n; j++) {
            int s = __shfl_sync(~0u, s_my, j);
            float exv = s_ex[w][j * 8 + (lane >> 2)];
            float2 hv = *(const float2*)&g_h1[(size_t)s * D1 + 2 * lane];
            accx = fmaf(hv.x, exv, accx);
            accy = fmaf(hv.y, exv, accy);
        }
        __syncwarp();
    }
    // reduce per-head denominators (all lanes get all heads)
#pragma unroll
    for (int h = 0; h < 8; h++) {
#pragma unroll
        for (int off = 16; off; off >>= 1)
            dsum[h] += __shfl_xor_sync(~0u, dsum[h], off);
    }
    // ---- fused node2: my channels are (2*lane, 2*lane+1), head = lane>>2
    float rc = 1.f / (dsum[lane >> 2] + 1e-16f);
    float2 bb = *(const float2*)&b1[2 * lane];
    float h2x = elu1(fmaf(accx, rc, bb.x));
    float h2y = elu1(fmaf(accy, rc, bb.y));
    float p[C2];
#pragma unroll
    for (int c = 0; c < C2; c++)
        p[c] = fmaf(h2x, __ldg(&W2[(2 * lane) * C2 + c]),
               h2y * __ldg(&W2[(2 * lane + 1) * C2 + c]));
#pragma unroll
    for (int off = 16; off; off >>= 1)
#pragma unroll
        for (int c = 0; c < C2; c++) p[c] += __shfl_xor_sync(~0u, p[c], off);
    float al = 0.f, ar = 0.f;
#pragma unroll
    for (int c = 0; c < C2; c++) {
        al = fmaf(p[c], __ldg(&as2[c]), al);
        ar = fmaf(p[c], __ldg(&ad2[c]), ar);
    }
    if (lane == 0) { g_al2[d] = al; g_ar2[d] = ar; }
    if (lane < C2) {
        float v = p[0];
#pragma unroll
        for (int c = 1; c < C2; c++) if (lane == c) v = p[c];
        g_z2[d * C2 + lane] = v;
    }
}

// layer-2 aggregation + fused log_softmax
__global__ void agg2_kernel(const float* __restrict__ b2, float* __restrict__ out) {
    int d = (blockIdx.x * blockDim.x + threadIdx.x) >> 5;
    int lane = threadIdx.x & 31;
    if (d >= NN) return;
    int beg = g_off[d], end = g_off[d + 1];
    float ard = g_ar2[d];
    float acc = 0.f, dsum = 0.f;
    for (int b = beg; b < end; b += 32) {
        int n = min(32, end - b);
        int s_my = (b + lane < end) ? g_esrc[b + lane] : 0;
        float ex_my = (b + lane < end) ? fast_exp(lrelu(g_al2[s_my] + ard)) : 0.f;
        dsum += ex_my;
        for (int j = 0; j < n; j++) {
            int   s  = __shfl_sync(~0u, s_my, j);
            float ex = __shfl_sync(~0u, ex_my, j);
            if (lane < C2) acc = fmaf(g_z2[s * C2 + lane], ex, acc);
        }
    }
#pragma unroll
    for (int off = 16; off; off >>= 1)
        dsum += __shfl_xor_sync(~0u, dsum, off);
    float rc = 1.f / (dsum + 1e-16f);
    float v = (lane < C2) ? fmaf(acc, rc, __ldg(&b2[lane])) : -1e30f;
    float m = v;
#pragma unroll
    for (int off = 8; off; off >>= 1)
        m = fmaxf(m, __shfl_xor_sync(~0u, m, off, 16));
    float s = (lane < C2) ? fast_exp(v - m) : 0.f;
#pragma unroll
    for (int off = 8; off; off >>= 1)
        s += __shfl_xor_sync(~0u, s, off, 16);
    float l = m + logf(s);
    if (lane < C2) out[(size_t)d * C2 + lane] = v - l;
}

// ---------------- launch ----------------
extern "C" void kernel_launch(void* const* d_in, const int* in_sizes, int n_in,
                              void* d_out, int out_size) {
    const float* x   = (const float*)d_in[0];
    const int*   ei  = (const int*)d_in[1];    // int32 (JAX x64 disabled)
    const float* W1  = (const float*)d_in[2];
    const float* as1 = (const float*)d_in[3];
    const float* ad1 = (const float*)d_in[4];
    const float* b1  = (const float*)d_in[5];
    const float* W2  = (const float*)d_in[6];
    const float* as2 = (const float*)d_in[7];
    const float* ad2 = (const float*)d_in[8];
    const float* b2  = (const float*)d_in[9];

    int E = in_sizes[1] / 2;
    const int* src = ei;
    const int* dst = ei + E;
    int tot = E + NN;

    hist_kernel   <<<(tot + 255) / 256, 256>>>(src, dst, E);            // 0
    scan_kernel   <<<1, 1024>>>();                                      // 1
    scatter_kernel<<<(tot + 255) / 256, 256>>>(src, dst, E);            // 2
    gemm1_kernel  <<<(NN + 63) / 64, 256>>>(x, W1, as1, ad1);           // 3 <- profiled
    agg1_kernel   <<<(NN * 32 + 255) / 256, 256>>>(b1, W2, as2, ad2);   // 4
    agg2_kernel   <<<(NN * 32 + 255) / 256, 256>>>(b2, (float*)d_out);  // 5
}

// round 9
// speedup vs baseline: 1.3330x; 1.3330x over previous
#include <cuda_runtime.h>
#include <cstdint>

#define NN   100000
#define FIN  512
#define H1   8
#define D1   64      // H1*C1
#define C2   10
#define EMAXSZ 1700000

// ---------------- scratch (no allocs allowed) ----------------
__device__ float g_h1 [NN * D1];     // layer1 features   25.6 MB
__device__ float g_al1[NN * H1];
__device__ float g_ar1[NN * H1];
__device__ float g_z2 [NN * C2];
__device__ float g_al2[NN];
__device__ float g_ar2[NN];
// sorted-by-dst edge structures
__device__ int   g_cnt [NN];         // zero at entry (module init; scan3 restores)
__device__ int   g_tmp [NN];
__device__ int   g_bsum[128];
__device__ int   g_bsum2[128];
__device__ int   g_off [NN + 1];
__device__ int   g_pos [NN];
__device__ int   g_esrc[EMAXSZ];

// ---------------- helpers ----------------
__device__ __forceinline__ float lrelu(float x) { return x > 0.f ? x : 0.2f * x; }

__device__ __forceinline__ float fast_exp(float x) {
    float t = x * 1.4426950408889634f;
    t = fminf(fmaxf(t, -126.f), 126.f);
    float fi = floorf(t);
    float f  = t - fi;
    int   i  = (int)fi;
    float p = 1.5403530e-4f;
    p = fmaf(p, f, 1.3333558e-3f);
    p = fmaf(p, f, 9.6181291e-3f);
    p = fmaf(p, f, 5.5504109e-2f);
    p = fmaf(p, f, 2.4022651e-1f);
    p = fmaf(p, f, 6.9314718e-1f);
    p = fmaf(p, f, 1.0f);
    return __uint_as_float(__float_as_uint(p) + ((unsigned)i << 23));
}

__device__ __forceinline__ float elu1(float x) {
    return x > 0.f ? x : fast_exp(fmaxf(x, -80.f)) - 1.f;
}

// packed fp32x2 FMA (Blackwell base ISA)
__device__ __forceinline__ unsigned long long rep2(float v) {
    unsigned long long r;
    asm("mov.b64 %0, {%1, %1};" : "=l"(r) : "f"(v));
    return r;
}
__device__ __forceinline__ void ffma2(unsigned long long& d,
                                      unsigned long long a, unsigned long long b) {
    asm("fma.rn.f32x2 %0, %1, %2, %0;" : "+l"(d) : "l"(a), "l"(b));
}
__device__ __forceinline__ float2 unpk(unsigned long long v) {
    float lo, hi;
    asm("mov.b64 {%0, %1}, %2;" : "=f"(lo), "=f"(hi) : "l"(v));
    return make_float2(lo, hi);
}

// ---------------- sort pipeline (launch-ordered, no spin-waits) ----------------
__device__ __forceinline__ bool edge_sd(const int* __restrict__ src,
                                        const int* __restrict__ dst,
                                        int e, int E, int& s, int& d) {
    if (e < E) { s = src[e]; d = dst[e]; }
    else       { s = d = e - E; }
    return (unsigned)s < NN && (unsigned)d < NN;
}

__global__ void hist_kernel(const int* __restrict__ src,
                            const int* __restrict__ dst, int E) {
    int e = blockIdx.x * blockDim.x + threadIdx.x;
    if (e >= E + NN) return;
    int s, d;
    if (!edge_sd(src, dst, e, E, s, d)) return;
    atomicAdd(&g_cnt[d], 1);
}

__global__ void scan1_kernel() {
    __shared__ int sm[1024];
    int tid = threadIdx.x, i = blockIdx.x * 1024 + tid;
    int v = (i < NN) ? g_cnt[i] : 0;
    sm[tid] = v;
    __syncthreads();
#pragma unroll
    for (int off = 1; off < 1024; off <<= 1) {
        int t = (tid >= off) ? sm[tid - off] : 0;
        __syncthreads();
        sm[tid] += t;
        __syncthreads();
    }
    if (i < NN) g_tmp[i] = sm[tid];
    if (tid == 1023) g_bsum[blockIdx.x] = sm[1023];
}

__global__ void scan2_kernel(int nb) {
    __shared__ int sm[128];
    int tid = threadIdx.x;
    int v = (tid < nb) ? g_bsum[tid] : 0;
    sm[tid] = v;
    __syncthreads();
#pragma unroll
    for (int off = 1; off < 128; off <<= 1) {
        int t = (tid >= off) ? sm[tid - off] : 0;
        __syncthreads();
        sm[tid] += t;
        __syncthreads();
    }
    if (tid < nb) g_bsum2[tid] = sm[tid] - v;   // exclusive
}

// finalize offsets; zero g_cnt for the next call (self-restoring state)
__global__ void scan3_kernel() {
    int i = blockIdx.x * 1024 + threadIdx.x;
    if (i < NN) {
        int c    = g_cnt[i];
        int incl = g_tmp[i] + g_bsum2[blockIdx.x];
        g_off[i + 1] = incl;
        g_pos[i]     = incl - c;
        g_cnt[i]     = 0;
        if (i == 0) g_off[0] = 0;
    }
}

__global__ void scatter_kernel(const int* __restrict__ src,
                               const int* __restrict__ dst, int E) {
    int e = blockIdx.x * blockDim.x + threadIdx.x;
    if (e >= E + NN) return;
    int s, d;
    if (!edge_sd(src, dst, e, E, s, d)) return;
    int p = atomicAdd(&g_pos[d], 1);
    g_esrc[p] = s;
}

// ---------------- compute kernels ----------------
// W-stationary GEMM: full W1 (512x64 fp32 = 128KB) in smem, thread = row.
// Inner loop: LDS.128 broadcast (ulonglong2) + FFMA2. Fused attention epilogue.
#define GSMEM (131072 + 512)
__global__ void __launch_bounds__(256, 1)
gemm1_kernel(const float* __restrict__ x, const float* __restrict__ W,
             const float* __restrict__ a_src, const float* __restrict__ a_dst) {
    extern __shared__ float sW[];            // [512*64] + as[64] + ad[64]
    float* s_as = sW + 32768;
    float* s_ad = sW + 32832;
    int t = threadIdx.x;
    for (int i = t; i < 8192; i += 256)
        ((float4*)sW)[i] = ((const float4*)W)[i];
    if (t < 64) { s_as[t] = a_src[t]; s_ad[t] = a_dst[t]; }
    __syncthreads();

    int row = blockIdx.x * 256 + t;
    bool rok = row < NN;
    const float4* xr = (const float4*)(x + (size_t)(rok ? row : 0) * FIN);

    unsigned long long acc[32];
#pragma unroll
    for (int c = 0; c < 32; c++) acc[c] = 0ull;

    float4 nv0 = xr[0], nv1 = xr[1];
    for (int k0 = 0; k0 < FIN; k0 += 8) {
        float4 xv0 = nv0, xv1 = nv1;
        if (k0 + 8 < FIN) { nv0 = xr[(k0 >> 2) + 2]; nv1 = xr[(k0 >> 2) + 3]; }
        float xk[8] = { xv0.x, xv0.y, xv0.z, xv0.w, xv1.x, xv1.y, xv1.z, xv1.w };
#pragma unroll
        for (int j = 0; j < 8; j++) {
            unsigned long long a = rep2(xk[j]);
            const ulonglong2* wrow = (const ulonglong2*)(sW + (k0 + j) * D1);
#pragma unroll
            for (int c = 0; c < 16; c++) {
                ulonglong2 w2 = wrow[c];
                ffma2(acc[2 * c],     a, w2.x);
                ffma2(acc[2 * c + 1], a, w2.y);
            }
        }
    }

    if (rok) {
        float4* hout = (float4*)(g_h1 + (size_t)row * D1);
#pragma unroll
        for (int q = 0; q < 16; q++) {
            float2 a = unpk(acc[2 * q]), bq = unpk(acc[2 * q + 1]);
            hout[q] = make_float4(a.x, a.y, bq.x, bq.y);
        }
        float al[8], ar[8];
#pragma unroll
        for (int h = 0; h < 8; h++) {
            float sa = 0.f, sd = 0.f;
#pragma unroll
            for (int c = 0; c < 4; c++) {
                float2 vv = unpk(acc[h * 4 + c]);
                sa = fmaf(vv.x, s_as[h * 8 + 2 * c],     sa);
                sa = fmaf(vv.y, s_as[h * 8 + 2 * c + 1], sa);
                sd = fmaf(vv.x, s_ad[h * 8 + 2 * c],     sd);
                sd = fmaf(vv.y, s_ad[h * 8 + 2 * c + 1], sd);
            }
            al[h] = sa; ar[h] = sd;
        }
        float4* alo = (float4*)(g_al1 + row * H1);
        float4* aro = (float4*)(g_ar1 + row * H1);
        alo[0] = make_float4(al[0], al[1], al[2], al[3]);
        alo[1] = make_float4(al[4], al[5], al[6], al[7]);
        aro[0] = make_float4(ar[0], ar[1], ar[2], ar[3]);
        aro[1] = make_float4(ar[4], ar[5], ar[6], ar[7]);
    }
}

// layer-1 aggregation + FUSED layer-2 node prep
__global__ void agg1_kernel(const float* __restrict__ b1, const float* __restrict__ W2,
                            const float* __restrict__ as2, const float* __restrict__ ad2) {
    __shared__ float s_ex[8][256];
    int gw = (blockIdx.x * blockDim.x + threadIdx.x) >> 5;
    int w  = (threadIdx.x >> 5);
    int lane = threadIdx.x & 31;
    if (gw >= NN) return;
    int d = gw;
    int beg = g_off[d], end = g_off[d + 1];
    float4 ar0 = *(const float4*)&g_ar1[d * H1];
    float4 ar1 = *(const float4*)&g_ar1[d * H1 + 4];
    float dsum[8];
#pragma unroll
    for (int h = 0; h < 8; h++) dsum[h] = 0.f;
    float accx = 0.f, accy = 0.f;

    for (int b = beg; b < end; b += 32) {
        int n = min(32, end - b);
        int s_my = (lane < n) ? g_esrc[b + lane] : 0;
        if (lane < n) {
            float4 a0 = *(const float4*)&g_al1[s_my * H1];
            float4 a1 = *(const float4*)&g_al1[s_my * H1 + 4];
            float ex0 = fast_exp(lrelu(a0.x + ar0.x));
            float ex1 = fast_exp(lrelu(a0.y + ar0.y));
            float ex2 = fast_exp(lrelu(a0.z + ar0.z));
            float ex3 = fast_exp(lrelu(a0.w + ar0.w));
            float ex4 = fast_exp(lrelu(a1.x + ar1.x));
            float ex5 = fast_exp(lrelu(a1.y + ar1.y));
            float ex6 = fast_exp(lrelu(a1.z + ar1.z));
            float ex7 = fast_exp(lrelu(a1.w + ar1.w));
            dsum[0] += ex0; dsum[1] += ex1; dsum[2] += ex2; dsum[3] += ex3;
            dsum[4] += ex4; dsum[5] += ex5; dsum[6] += ex6; dsum[7] += ex7;
            *(float4*)&s_ex[w][lane * 8]     = make_float4(ex0, ex1, ex2, ex3);
            *(float4*)&s_ex[w][lane * 8 + 4] = make_float4(ex4, ex5, ex6, ex7);
        }
        __syncwarp();
        for (int j = 0; j < n; j++) {
            int s = __shfl_sync(~0u, s_my, j);
            float exv = s_ex[w][j * 8 + (lane >> 2)];
            float2 hv = *(const float2*)&g_h1[(size_t)s * D1 + 2 * lane];
            accx = fmaf(hv.x, exv, accx);
            accy = fmaf(hv.y, exv, accy);
        }
        __syncwarp();
    }
#pragma unroll
    for (int h = 0; h < 8; h++) {
#pragma unroll
        for (int off = 16; off; off >>= 1)
            dsum[h] += __shfl_xor_sync(~0u, dsum[h], off);
    }
    float rc = 1.f / (dsum[lane >> 2] + 1e-16f);
    float2 bb = *(const float2*)&b1[2 * lane];
    float h2x = elu1(fmaf(accx, rc, bb.x));
    float h2y = elu1(fmaf(accy, rc, bb.y));
    float p[C2];
#pragma unroll
    for (int c = 0; c < C2; c++)
        p[c] = fmaf(h2x, __ldg(&W2[(2 * lane) * C2 + c]),
               h2y * __ldg(&W2[(2 * lane + 1) * C2 + c]));
#pragma unroll
    for (int off = 16; off; off >>= 1)
#pragma unroll
        for (int c = 0; c < C2; c++) p[c] += __shfl_xor_sync(~0u, p[c], off);
    float al = 0.f, ar = 0.f;
#pragma unroll
    for (int c = 0; c < C2; c++) {
        al = fmaf(p[c], __ldg(&as2[c]), al);
        ar = fmaf(p[c], __ldg(&ad2[c]), ar);
    }
    if (lane == 0) { g_al2[d] = al; g_ar2[d] = ar; }
    if (lane < C2) {
        float v = p[0];
#pragma unroll
        for (int c = 1; c < C2; c++) if (lane == c) v = p[c];
        g_z2[d * C2 + lane] = v;
    }
}

// layer-2 aggregation + fused log_softmax
__global__ void agg2_kernel(const float* __restrict__ b2, float* __restrict__ out) {
    int d = (blockIdx.x * blockDim.x + threadIdx.x) >> 5;
    int lane = threadIdx.x & 31;
    if (d >= NN) return;
    int beg = g_off[d], end = g_off[d + 1];
    float ard = g_ar2[d];
    float acc = 0.f, dsum = 0.f;
    for (int b = beg; b < end; b += 32) {
        int n = min(32, end - b);
        int s_my = (b + lane < end) ? g_esrc[b + lane] : 0;
        float ex_my = (b + lane < end) ? fast_exp(lrelu(g_al2[s_my] + ard)) : 0.f;
        dsum += ex_my;
        for (int j = 0; j < n; j++) {
            int   s  = __shfl_sync(~0u, s_my, j);
            float ex = __shfl_sync(~0u, ex_my, j);
            if (lane < C2) acc = fmaf(g_z2[s * C2 + lane], ex, acc);
        }
    }
#pragma unroll
    for (int off = 16; off; off >>= 1)
        dsum += __shfl_xor_sync(~0u, dsum, off);
    float rc = 1.f / (dsum + 1e-16f);
    float v = (lane < C2) ? fmaf(acc, rc, __ldg(&b2[lane])) : -1e30f;
    float m = v;
#pragma unroll
    for (int off = 8; off; off >>= 1)
        m = fmaxf(m, __shfl_xor_sync(~0u, m, off, 16));
    float s = (lane < C2) ? fast_exp(v - m) : 0.f;
#pragma unroll
    for (int off = 8; off; off >>= 1)
        s += __shfl_xor_sync(~0u, s, off, 16);
    float l = m + logf(s);
    if (lane < C2) out[(size_t)d * C2 + lane] = v - l;
}

// ---------------- launch ----------------
extern "C" void kernel_launch(void* const* d_in, const int* in_sizes, int n_in,
                              void* d_out, int out_size) {
    const float* x   = (const float*)d_in[0];
    const int*   ei  = (const int*)d_in[1];    // int32 (JAX x64 disabled)
    const float* W1  = (const float*)d_in[2];
    const float* as1 = (const float*)d_in[3];
    const float* ad1 = (const float*)d_in[4];
    const float* b1  = (const float*)d_in[5];
    const float* W2  = (const float*)d_in[6];
    const float* as2 = (const float*)d_in[7];
    const float* ad2 = (const float*)d_in[8];
    const float* b2  = (const float*)d_in[9];

    int E = in_sizes[1] / 2;
    const int* src = ei;
    const int* dst = ei + E;
    int tot = E + NN;
    int nb1 = (NN + 1023) / 1024;

    cudaFuncSetAttribute(gemm1_kernel,
                         cudaFuncAttributeMaxDynamicSharedMemorySize, GSMEM);

    hist_kernel   <<<(tot + 255) / 256, 256>>>(src, dst, E);            // 0
    scan1_kernel  <<<nb1, 1024>>>();                                    // 1
    scan2_kernel  <<<1, 128>>>(nb1);                                    // 2
    gemm1_kernel  <<<(NN + 255) / 256, 256, GSMEM>>>(x, W1, as1, ad1);  // 3 <- profiled
    scan3_kernel  <<<nb1, 1024>>>();                                    // 4
    scatter_kernel<<<(tot + 255) / 256, 256>>>(src, dst, E);            // 5
    agg1_kernel   <<<(NN * 32 + 255) / 256, 256>>>(b1, W2, as2, ad2);   // 6
    agg2_kernel   <<<(NN * 32 + 255) / 256, 256>>>(b2, (float*)d_out);  // 7
}

// round 10
// speedup vs baseline: 2.1357x; 1.6022x over previous
#include <cuda_runtime.h>
#include <cuda_bf16.h>
#include <cstdint>

#define NN   100000
#define FIN  512
#define H1   8
#define D1   64      // H1*C1
#define C2   10
#define EMAXSZ 1700000
#define KSTEPS 32    // 512 / 16

// ---------------- scratch (no allocs allowed) ----------------
__device__ float g_h1 [NN * D1];     // layer1 features   25.6 MB
__device__ float g_al1[NN * H1];
__device__ float g_ar1[NN * H1];
__device__ float g_z2 [NN * C2];
__device__ float g_al2[NN];
__device__ float g_ar2[NN];
// B fragments (bf16 hi/lo) in mma layout: [(ks*8+t)*64 + 2*lane + {0,1}]
__device__ uint32_t g_bh[KSTEPS * 8 * 64];
__device__ uint32_t g_bl[KSTEPS * 8 * 64];
// sorted-by-dst edge structures
__device__ int   g_cnt [NN];         // zero at entry (module init; scan3 restores)
__device__ int   g_tmp [NN];
__device__ int   g_bsum[128];
__device__ int   g_bsum2[128];
__device__ int   g_off [NN + 1];
__device__ int   g_pos [NN];
__device__ int   g_esrc[EMAXSZ];

// ---------------- helpers ----------------
__device__ __forceinline__ float lrelu(float x) { return x > 0.f ? x : 0.2f * x; }

__device__ __forceinline__ float fast_exp(float x) {
    float t = x * 1.4426950408889634f;
    t = fminf(fmaxf(t, -126.f), 126.f);
    float fi = floorf(t);
    float f  = t - fi;
    int   i  = (int)fi;
    float p = 1.5403530e-4f;
    p = fmaf(p, f, 1.3333558e-3f);
    p = fmaf(p, f, 9.6181291e-3f);
    p = fmaf(p, f, 5.5504109e-2f);
    p = fmaf(p, f, 2.4022651e-1f);
    p = fmaf(p, f, 6.9314718e-1f);
    p = fmaf(p, f, 1.0f);
    return __uint_as_float(__float_as_uint(p) + ((unsigned)i << 23));
}

__device__ __forceinline__ float elu1(float x) {
    return x > 0.f ? x : fast_exp(fmaxf(x, -80.f)) - 1.f;
}

__device__ __forceinline__ uint32_t pkbf2(float a, float b) {
    __nv_bfloat162 t = __floats2bfloat162_rn(a, b);
    return *(uint32_t*)&t;
}
__device__ __forceinline__ float bf2f(float v) {        // round-trip through bf16
    return __bfloat162float(__float2bfloat16_rn(v));
}

// m16n8k16 row.col bf16 -> f32 accum
__device__ __forceinline__ void mma16816(float* c, const uint32_t* a,
                                         uint32_t b0, uint32_t b1) {
    asm volatile(
        "mma.sync.aligned.m16n8k16.row.col.f32.bf16.bf16.f32 "
        "{%0,%1,%2,%3}, {%4,%5,%6,%7}, {%8,%9}, {%0,%1,%2,%3};"
        : "+f"(c[0]), "+f"(c[1]), "+f"(c[2]), "+f"(c[3])
        : "r"(a[0]), "r"(a[1]), "r"(a[2]), "r"(a[3]), "r"(b0), "r"(b1));
}

// ---------------- B fragment precompute ----------------
// thread = (ks, t, lane): B tile is W[k0..k0+15][n0..n0+7] col-major fragments.
__global__ void bprep_kernel(const float* __restrict__ W) {
    int id = blockIdx.x * blockDim.x + threadIdx.x;   // 8192 threads
    if (id >= KSTEPS * 8 * 32) return;
    int l  = id & 31;
    int t  = (id >> 5) & 7;
    int ks = id >> 8;
    int k0 = ks * 16, n0 = t * 8;
    int n  = n0 + (l >> 2);
    int ka = k0 + 2 * (l & 3);
    float w00 = W[(ka)     * D1 + n], w01 = W[(ka + 1) * D1 + n];
    float w08 = W[(ka + 8) * D1 + n], w09 = W[(ka + 9) * D1 + n];
    float h00 = bf2f(w00), h01 = bf2f(w01), h08 = bf2f(w08), h09 = bf2f(w09);
    int idx = (ks * 8 + t) * 64 + 2 * l;
    g_bh[idx]     = pkbf2(w00, w01);
    g_bh[idx + 1] = pkbf2(w08, w09);
    g_bl[idx]     = pkbf2(w00 - h00, w01 - h01);
    g_bl[idx + 1] = pkbf2(w08 - h08, w09 - h09);
}

// ---------------- sort pipeline (launch-ordered, no spin-waits) ----------------
__device__ __forceinline__ bool edge_sd(const int* __restrict__ src,
                                        const int* __restrict__ dst,
                                        int e, int E, int& s, int& d) {
    if (e < E) { s = src[e]; d = dst[e]; }
    else       { s = d = e - E; }
    return (unsigned)s < NN && (unsigned)d < NN;
}

__global__ void hist_kernel(const int* __restrict__ src,
                            const int* __restrict__ dst, int E) {
    int e = blockIdx.x * blockDim.x + threadIdx.x;
    if (e >= E + NN) return;
    int s, d;
    if (!edge_sd(src, dst, e, E, s, d)) return;
    atomicAdd(&g_cnt[d], 1);
}

__global__ void scan1_kernel() {
    __shared__ int sm[1024];
    int tid = threadIdx.x, i = blockIdx.x * 1024 + tid;
    int v = (i < NN) ? g_cnt[i] : 0;
    sm[tid] = v;
    __syncthreads();
#pragma unroll
    for (int off = 1; off < 1024; off <<= 1) {
        int t = (tid >= off) ? sm[tid - off] : 0;
        __syncthreads();
        sm[tid] += t;
        __syncthreads();
    }
    if (i < NN) g_tmp[i] = sm[tid];
    if (tid == 1023) g_bsum[blockIdx.x] = sm[1023];
}

__global__ void scan2_kernel(int nb) {
    __shared__ int sm[128];
    int tid = threadIdx.x;
    int v = (tid < nb) ? g_bsum[tid] : 0;
    sm[tid] = v;
    __syncthreads();
#pragma unroll
    for (int off = 1; off < 128; off <<= 1) {
        int t = (tid >= off) ? sm[tid - off] : 0;
        __syncthreads();
        sm[tid] += t;
        __syncthreads();
    }
    if (tid < nb) g_bsum2[tid] = sm[tid] - v;   // exclusive
}

__global__ void scan3_kernel() {
    int i = blockIdx.x * 1024 + threadIdx.x;
    if (i < NN) {
        int c    = g_cnt[i];
        int incl = g_tmp[i] + g_bsum2[blockIdx.x];
        g_off[i + 1] = incl;
        g_pos[i]     = incl - c;
        g_cnt[i]     = 0;
        if (i == 0) g_off[0] = 0;
    }
}

__global__ void scatter_kernel(const int* __restrict__ src,
                               const int* __restrict__ dst, int E) {
    int e = blockIdx.x * blockDim.x + threadIdx.x;
    if (e >= E + NN) return;
    int s, d;
    if (!edge_sd(src, dst, e, E, s, d)) return;
    int p = atomicAdd(&g_pos[d], 1);
    g_esrc[p] = s;
}

// ---------------- tensor-core GEMM (split-bf16 mma.sync) ----------------
// warp owns 16 rows x 64 cols; block = 8 warps = 128 rows.
__global__ void __launch_bounds__(256, 2)
gemm1_kernel(const float* __restrict__ x,
             const float* __restrict__ a_src, const float* __restrict__ a_dst) {
    __shared__ float s_as[64], s_ad[64];
    int tid = threadIdx.x, w = tid >> 5, l = tid & 31;
    if (tid < 64) { s_as[tid] = a_src[tid]; s_ad[tid] = a_dst[tid]; }
    __syncthreads();

    int m0   = blockIdx.x * 128 + w * 16;
    int row0 = m0 + (l >> 2);
    int row1 = row0 + 8;
    const float* xr0 = x + (size_t)(row0 < NN ? row0 : 0) * FIN + 2 * (l & 3);
    const float* xr1 = x + (size_t)(row1 < NN ? row1 : 0) * FIN + 2 * (l & 3);

    float c[8][4];
#pragma unroll
    for (int t = 0; t < 8; t++)
#pragma unroll
        for (int q = 0; q < 4; q++) c[t][q] = 0.f;

    for (int ks = 0; ks < KSTEPS; ks++) {
        int k0 = ks * 16;
        float2 v0 = *(const float2*)(xr0 + k0);
        float2 v1 = *(const float2*)(xr1 + k0);
        float2 v2 = *(const float2*)(xr0 + k0 + 8);
        float2 v3 = *(const float2*)(xr1 + k0 + 8);
        float h0x = bf2f(v0.x), h0y = bf2f(v0.y);
        float h1x = bf2f(v1.x), h1y = bf2f(v1.y);
        float h2x = bf2f(v2.x), h2y = bf2f(v2.y);
        float h3x = bf2f(v3.x), h3y = bf2f(v3.y);
        uint32_t ah[4] = { pkbf2(h0x, h0y), pkbf2(h1x, h1y),
                           pkbf2(h2x, h2y), pkbf2(h3x, h3y) };
        uint32_t al[4] = { pkbf2(v0.x - h0x, v0.y - h0y),
                           pkbf2(v1.x - h1x, v1.y - h1y),
                           pkbf2(v2.x - h2x, v2.y - h2y),
                           pkbf2(v3.x - h3x, v3.y - h3y) };
        const uint2* bh = (const uint2*)(g_bh + ks * 8 * 64) + l;
        const uint2* bl = (const uint2*)(g_bl + ks * 8 * 64) + l;
#pragma unroll
        for (int t = 0; t < 8; t++) {
            uint2 b_hi = bh[t * 32];
            uint2 b_lo = bl[t * 32];
            mma16816(c[t], ah, b_hi.x, b_hi.y);   // hi*hi
            mma16816(c[t], ah, b_lo.x, b_lo.y);   // hi*lo
            mma16816(c[t], al, b_hi.x, b_hi.y);   // lo*hi
        }
    }

    // epilogue: store h1 + fused attention terms (head h == n-tile t)
    bool ok0 = row0 < NN, ok1 = row1 < NN;
    float al0[8], ar0[8], al1[8], ar1[8];
#pragma unroll
    for (int t = 0; t < 8; t++) {
        int col = t * 8 + 2 * (l & 3);
        if (ok0) *(float2*)&g_h1[(size_t)row0 * D1 + col] = make_float2(c[t][0], c[t][1]);
        if (ok1) *(float2*)&g_h1[(size_t)row1 * D1 + col] = make_float2(c[t][2], c[t][3]);
        float sa0 = c[t][0] * s_as[col] + c[t][1] * s_as[col + 1];
        float sd0 = c[t][0] * s_ad[col] + c[t][1] * s_ad[col + 1];
        float sa1 = c[t][2] * s_as[col] + c[t][3] * s_as[col + 1];
        float sd1 = c[t][2] * s_ad[col] + c[t][3] * s_ad[col + 1];
#pragma unroll
        for (int off = 1; off < 4; off <<= 1) {
            sa0 += __shfl_xor_sync(~0u, sa0, off);
            sd0 += __shfl_xor_sync(~0u, sd0, off);
            sa1 += __shfl_xor_sync(~0u, sa1, off);
            sd1 += __shfl_xor_sync(~0u, sd1, off);
        }
        al0[t] = sa0; ar0[t] = sd0; al1[t] = sa1; ar1[t] = sd1;
    }
    if ((l & 3) == 0) {
#pragma unroll
        for (int t = 0; t < 8; t++) {
            if (ok0) { g_al1[row0 * H1 + t] = al0[t]; g_ar1[row0 * H1 + t] = ar0[t]; }
            if (ok1) { g_al1[row1 * H1 + t] = al1[t]; g_ar1[row1 * H1 + t] = ar1[t]; }
        }
    }
}

// layer-1 aggregation + FUSED layer-2 node prep (unchanged)
__global__ void agg1_kernel(const float* __restrict__ b1, const float* __restrict__ W2,
                            const float* __restrict__ as2, const float* __restrict__ ad2) {
    __shared__ float s_ex[8][256];
    int gw = (blockIdx.x * blockDim.x + threadIdx.x) >> 5;
    int w  = (threadIdx.x >> 5);
    int lane = threadIdx.x & 31;
    if (gw >= NN) return;
    int d = gw;
    int beg = g_off[d], end = g_off[d + 1];
    float4 ar0 = *(const float4*)&g_ar1[d * H1];
    float4 ar1 = *(const float4*)&g_ar1[d * H1 + 4];
    float dsum[8];
#pragma unroll
    for (int h = 0; h < 8; h++) dsum[h] = 0.f;
    float accx = 0.f, accy = 0.f;

    for (int b = beg; b < end; b += 32) {
        int n = min(32, end - b);
        int s_my = (lane < n) ? g_esrc[b + lane] : 0;
        if (lane < n) {
            float4 a0 = *(const float4*)&g_al1[s_my * H1];
            float4 a1 = *(const float4*)&g_al1[s_my * H1 + 4];
            float ex0 = fast_exp(lrelu(a0.x + ar0.x));
            float ex1 = fast_exp(lrelu(a0.y + ar0.y));
            float ex2 = fast_exp(lrelu(a0.z + ar0.z));
            float ex3 = fast_exp(lrelu(a0.w + ar0.w));
            float ex4 = fast_exp(lrelu(a1.x + ar1.x));
            float ex5 = fast_exp(lrelu(a1.y + ar1.y));
            float ex6 = fast_exp(lrelu(a1.z + ar1.z));
            float ex7 = fast_exp(lrelu(a1.w + ar1.w));
            dsum[0] += ex0; dsum[1] += ex1; dsum[2] += ex2; dsum[3] += ex3;
            dsum[4] += ex4; dsum[5] += ex5; dsum[6] += ex6; dsum[7] += ex7;
            *(float4*)&s_ex[w][lane * 8]     = make_float4(ex0, ex1, ex2, ex3);
            *(float4*)&s_ex[w][lane * 8 + 4] = make_float4(ex4, ex5, ex6, ex7);
        }
        __syncwarp();
        for (int j = 0; j < n; j++) {
            int s = __shfl_sync(~0u, s_my, j);
            float exv = s_ex[w][j * 8 + (lane >> 2)];
            float2 hv = *(const float2*)&g_h1[(size_t)s * D1 + 2 * lane];
            accx = fmaf(hv.x, exv, accx);
            accy = fmaf(hv.y, exv, accy);
        }
        __syncwarp();
    }
#pragma unroll
    for (int h = 0; h < 8; h++) {
#pragma unroll
        for (int off = 16; off; off >>= 1)
            dsum[h] += __shfl_xor_sync(~0u, dsum[h], off);
    }
    float rc = 1.f / (dsum[lane >> 2] + 1e-16f);
    float2 bb = *(const float2*)&b1[2 * lane];
    float h2x = elu1(fmaf(accx, rc, bb.x));
    float h2y = elu1(fmaf(accy, rc, bb.y));
    float p[C2];
#pragma unroll
    for (int c = 0; c < C2; c++)
        p[c] = fmaf(h2x, __ldg(&W2[(2 * lane) * C2 + c]),
               h2y * __ldg(&W2[(2 * lane + 1) * C2 + c]));
#pragma unroll
    for (int off = 16; off; off >>= 1)
#pragma unroll
        for (int c = 0; c < C2; c++) p[c] += __shfl_xor_sync(~0u, p[c], off);
    float al = 0.f, ar = 0.f;
#pragma unroll
    for (int c = 0; c < C2; c++) {
        al = fmaf(p[c], __ldg(&as2[c]), al);
        ar = fmaf(p[c], __ldg(&ad2[c]), ar);
    }
    if (lane == 0) { g_al2[d] = al; g_ar2[d] = ar; }
    if (lane < C2) {
        float v = p[0];
#pragma unroll
        for (int c = 1; c < C2; c++) if (lane == c) v = p[c];
        g_z2[d * C2 + lane] = v;
    }
}

// layer-2 aggregation + fused log_softmax (unchanged)
__global__ void agg2_kernel(const float* __restrict__ b2, float* __restrict__ out) {
    int d = (blockIdx.x * blockDim.x + threadIdx.x) >> 5;
    int lane = threadIdx.x & 31;
    if (d >= NN) return;
    int beg = g_off[d], end = g_off[d + 1];
    float ard = g_ar2[d];
    float acc = 0.f, dsum = 0.f;
    for (int b = beg; b < end; b += 32) {
        int n = min(32, end - b);
        int s_my = (b + lane < end) ? g_esrc[b + lane] : 0;
        float ex_my = (b + lane < end) ? fast_exp(lrelu(g_al2[s_my] + ard)) : 0.f;
        dsum += ex_my;
        for (int j = 0; j < n; j++) {
            int   s  = __shfl_sync(~0u, s_my, j);
            float ex = __shfl_sync(~0u, ex_my, j);
            if (lane < C2) acc = fmaf(g_z2[s * C2 + lane], ex, acc);
        }
    }
#pragma unroll
    for (int off = 16; off; off >>= 1)
        dsum += __shfl_xor_sync(~0u, dsum, off);
    float rc = 1.f / (dsum + 1e-16f);
    float v = (lane < C2) ? fmaf(acc, rc, __ldg(&b2[lane])) : -1e30f;
    float m = v;
#pragma unroll
    for (int off = 8; off; off >>= 1)
        m = fmaxf(m, __shfl_xor_sync(~0u, m, off, 16));
    float s = (lane < C2) ? fast_exp(v - m) : 0.f;
#pragma unroll
    for (int off = 8; off; off >>= 1)
        s += __shfl_xor_sync(~0u, s, off, 16);
    float l = m + logf(s);
    if (lane < C2) out[(size_t)d * C2 + lane] = v - l;
}

// ---------------- launch ----------------
extern "C" void kernel_launch(void* const* d_in, const int* in_sizes, int n_in,
                              void* d_out, int out_size) {
    const float* x   = (const float*)d_in[0];
    const int*   ei  = (const int*)d_in[1];    // int32 (JAX x64 disabled)
    const float* W1  = (const float*)d_in[2];
    const float* as1 = (const float*)d_in[3];
    const float* ad1 = (const float*)d_in[4];
    const float* b1  = (const float*)d_in[5];
    const float* W2  = (const float*)d_in[6];
    const float* as2 = (const float*)d_in[7];
    const float* ad2 = (const float*)d_in[8];
    const float* b2  = (const float*)d_in[9];

    int E = in_sizes[1] / 2;
    const int* src = ei;
    const int* dst = ei + E;
    int tot = E + NN;
    int nb1 = (NN + 1023) / 1024;

    bprep_kernel  <<<32, 256>>>(W1);                                    // 0
    hist_kernel   <<<(tot + 255) / 256, 256>>>(src, dst, E);            // 1
    scan1_kernel  <<<nb1, 1024>>>();                                    // 2
    gemm1_kernel  <<<(NN + 127) / 128, 256>>>(x, as1, ad1);             // 3 <- profiled
    scan2_kernel  <<<1, 128>>>(nb1);                                    // 4
    scan3_kernel  <<<nb1, 1024>>>();                                    // 5
    scatter_kernel<<<(tot + 255) / 256, 256>>>(src, dst, E);            // 6
    agg1_kernel   <<<(NN * 32 + 255) / 256, 256>>>(b1, W2, as2, ad2);   // 7
    agg2_kernel   <<<(NN * 32 + 255) / 256, 256>>>(b2, (float*)d_out);  // 8
}

// round 11
// speedup vs baseline: 2.3783x; 1.1136x over previous
#include <cuda_runtime.h>
#include <cuda_bf16.h>
#include <cstdint>

#define NN   100000
#define FIN  512
#define H1   8
#define D1   64      // H1*C1
#define C2   10
#define EMAXSZ 1700000
#define KSTEPS 32    // 512 / 16

// ---------------- scratch (no allocs allowed) ----------------
__device__ float g_h1 [NN * D1];     // layer1 features   25.6 MB
__device__ float g_al1[NN * H1];
__device__ float g_ar1[NN * H1];
__device__ float g_z2 [NN * C2];
__device__ float g_al2[NN];
__device__ float g_ar2[NN];
// B fragments (bf16 hi/lo) in mma layout: [(ks*8+t)*64 + 2*lane + {0,1}]
__device__ uint32_t g_bh[KSTEPS * 8 * 64];
__device__ uint32_t g_bl[KSTEPS * 8 * 64];
// sorted-by-dst edge structures
__device__ int   g_cnt [NN];         // zero at entry (module init; scan3 restores)
__device__ int   g_tmp [NN];
__device__ int   g_bsum[128];
__device__ int   g_bsum2[128];
__device__ int   g_off [NN + 1];
__device__ int   g_pos [NN];
__device__ int   g_esrc[EMAXSZ];

// ---------------- helpers ----------------
__device__ __forceinline__ float lrelu(float x) { return x > 0.f ? x : 0.2f * x; }

__device__ __forceinline__ float fast_exp(float x) {
    float t = x * 1.4426950408889634f;
    t = fminf(fmaxf(t, -126.f), 126.f);
    float fi = floorf(t);
    float f  = t - fi;
    int   i  = (int)fi;
    float p = 1.5403530e-4f;
    p = fmaf(p, f, 1.3333558e-3f);
    p = fmaf(p, f, 9.6181291e-3f);
    p = fmaf(p, f, 5.5504109e-2f);
    p = fmaf(p, f, 2.4022651e-1f);
    p = fmaf(p, f, 6.9314718e-1f);
    p = fmaf(p, f, 1.0f);
    return __uint_as_float(__float_as_uint(p) + ((unsigned)i << 23));
}

__device__ __forceinline__ float elu1(float x) {
    return x > 0.f ? x : fast_exp(fmaxf(x, -80.f)) - 1.f;
}

__device__ __forceinline__ uint32_t pkbf2(float a, float b) {
    __nv_bfloat162 t = __floats2bfloat162_rn(a, b);
    return *(uint32_t*)&t;
}
__device__ __forceinline__ float bf2f(float v) {
    return __bfloat162float(__float2bfloat16_rn(v));
}

// m16n8k16 row.col bf16 -> f32 accum
__device__ __forceinline__ void mma16816(float* c, const uint32_t* a,
                                         uint32_t b0, uint32_t b1) {
    asm volatile(
        "mma.sync.aligned.m16n8k16.row.col.f32.bf16.bf16.f32 "
        "{%0,%1,%2,%3}, {%4,%5,%6,%7}, {%8,%9}, {%0,%1,%2,%3};"
        : "+f"(c[0]), "+f"(c[1]), "+f"(c[2]), "+f"(c[3])
        : "r"(a[0]), "r"(a[1]), "r"(a[2]), "r"(a[3]), "r"(b0), "r"(b1));
}

// ---------------- B fragment precompute ----------------
__global__ void bprep_kernel(const float* __restrict__ W) {
    int id = blockIdx.x * blockDim.x + threadIdx.x;   // 8192 threads
    if (id >= KSTEPS * 8 * 32) return;
    int l  = id & 31;
    int t  = (id >> 5) & 7;
    int ks = id >> 8;
    int k0 = ks * 16, n0 = t * 8;
    int n  = n0 + (l >> 2);
    int ka = k0 + 2 * (l & 3);
    float w00 = W[(ka)     * D1 + n], w01 = W[(ka + 1) * D1 + n];
    float w08 = W[(ka + 8) * D1 + n], w09 = W[(ka + 9) * D1 + n];
    float h00 = bf2f(w00), h01 = bf2f(w01), h08 = bf2f(w08), h09 = bf2f(w09);
    int idx = (ks * 8 + t) * 64 + 2 * l;
    g_bh[idx]     = pkbf2(w00, w01);
    g_bh[idx + 1] = pkbf2(w08, w09);
    g_bl[idx]     = pkbf2(w00 - h00, w01 - h01);
    g_bl[idx + 1] = pkbf2(w08 - h08, w09 - h09);
}

// ---------------- sort pipeline (launch-ordered, no spin-waits) ----------------
__device__ __forceinline__ bool edge_sd(const int* __restrict__ src,
                                        const int* __restrict__ dst,
                                        int e, int E, int& s, int& d) {
    if (e < E) { s = src[e]; d = dst[e]; }
    else       { s = d = e - E; }
    return (unsigned)s < NN && (unsigned)d < NN;
}

__global__ void hist_kernel(const int* __restrict__ src,
                            const int* __restrict__ dst, int E) {
    int e = blockIdx.x * blockDim.x + threadIdx.x;
    if (e >= E + NN) return;
    int s, d;
    if (!edge_sd(src, dst, e, E, s, d)) return;
    atomicAdd(&g_cnt[d], 1);
}

__global__ void scan1_kernel() {
    __shared__ int sm[1024];
    int tid = threadIdx.x, i = blockIdx.x * 1024 + tid;
    int v = (i < NN) ? g_cnt[i] : 0;
    sm[tid] = v;
    __syncthreads();
#pragma unroll
    for (int off = 1; off < 1024; off <<= 1) {
        int t = (tid >= off) ? sm[tid - off] : 0;
        __syncthreads();
        sm[tid] += t;
        __syncthreads();
    }
    if (i < NN) g_tmp[i] = sm[tid];
    if (tid == 1023) g_bsum[blockIdx.x] = sm[1023];
}

__global__ void scan2_kernel(int nb) {
    __shared__ int sm[128];
    int tid = threadIdx.x;
    int v = (tid < nb) ? g_bsum[tid] : 0;
    sm[tid] = v;
    __syncthreads();
#pragma unroll
    for (int off = 1; off < 128; off <<= 1) {
        int t = (tid >= off) ? sm[tid - off] : 0;
        __syncthreads();
        sm[tid] += t;
        __syncthreads();
    }
    if (tid < nb) g_bsum2[tid] = sm[tid] - v;   // exclusive
}

__global__ void scan3_kernel() {
    int i = blockIdx.x * 1024 + threadIdx.x;
    if (i < NN) {
        int c    = g_cnt[i];
        int incl = g_tmp[i] + g_bsum2[blockIdx.x];
        g_off[i + 1] = incl;
        g_pos[i]     = incl - c;
        g_cnt[i]     = 0;
        if (i == 0) g_off[0] = 0;
    }
}

__global__ void scatter_kernel(const int* __restrict__ src,
                               const int* __restrict__ dst, int E) {
    int e = blockIdx.x * blockDim.x + threadIdx.x;
    if (e >= E + NN) return;
    int s, d;
    if (!edge_sd(src, dst, e, E, s, d)) return;
    int p = atomicAdd(&g_pos[d], 1);
    g_esrc[p] = s;
}

// ---------------- tensor-core GEMM (split-bf16 mma.sync) ----------------
__global__ void __launch_bounds__(256, 2)
gemm1_kernel(const float* __restrict__ x,
             const float* __restrict__ a_src, const float* __restrict__ a_dst) {
    __shared__ float s_as[64], s_ad[64];
    int tid = threadIdx.x, w = tid >> 5, l = tid & 31;
    if (tid < 64) { s_as[tid] = a_src[tid]; s_ad[tid] = a_dst[tid]; }
    __syncthreads();

    int m0   = blockIdx.x * 128 + w * 16;
    int row0 = m0 + (l >> 2);
    int row1 = row0 + 8;
    const float* xr0 = x + (size_t)(row0 < NN ? row0 : 0) * FIN + 2 * (l & 3);
    const float* xr1 = x + (size_t)(row1 < NN ? row1 : 0) * FIN + 2 * (l & 3);

    float c[8][4];
#pragma unroll
    for (int t = 0; t < 8; t++)
#pragma unroll
        for (int q = 0; q < 4; q++) c[t][q] = 0.f;

    for (int ks = 0; ks < KSTEPS; ks++) {
        int k0 = ks * 16;
        float2 v0 = *(const float2*)(xr0 + k0);
        float2 v1 = *(const float2*)(xr1 + k0);
        float2 v2 = *(const float2*)(xr0 + k0 + 8);
        float2 v3 = *(const float2*)(xr1 + k0 + 8);
        float h0x = bf2f(v0.x), h0y = bf2f(v0.y);
        float h1x = bf2f(v1.x), h1y = bf2f(v1.y);
        float h2x = bf2f(v2.x), h2y = bf2f(v2.y);
        float h3x = bf2f(v3.x), h3y = bf2f(v3.y);
        uint32_t ah[4] = { pkbf2(h0x, h0y), pkbf2(h1x, h1y),
                           pkbf2(h2x, h2y), pkbf2(h3x, h3y) };
        uint32_t al[4] = { pkbf2(v0.x - h0x, v0.y - h0y),
                           pkbf2(v1.x - h1x, v1.y - h1y),
                           pkbf2(v2.x - h2x, v2.y - h2y),
                           pkbf2(v3.x - h3x, v3.y - h3y) };
        const uint2* bh = (const uint2*)(g_bh + ks * 8 * 64) + l;
        const uint2* bl = (const uint2*)(g_bl + ks * 8 * 64) + l;
#pragma unroll
        for (int t = 0; t < 8; t++) {
            uint2 b_hi = bh[t * 32];
            uint2 b_lo = bl[t * 32];
            mma16816(c[t], ah, b_hi.x, b_hi.y);
            mma16816(c[t], ah, b_lo.x, b_lo.y);
            mma16816(c[t], al, b_hi.x, b_hi.y);
        }
    }

    bool ok0 = row0 < NN, ok1 = row1 < NN;
    float al0[8], ar0[8], al1[8], ar1[8];
#pragma unroll
    for (int t = 0; t < 8; t++) {
        int col = t * 8 + 2 * (l & 3);
        if (ok0) *(float2*)&g_h1[(size_t)row0 * D1 + col] = make_float2(c[t][0], c[t][1]);
        if (ok1) *(float2*)&g_h1[(size_t)row1 * D1 + col] = make_float2(c[t][2], c[t][3]);
        float sa0 = c[t][0] * s_as[col] + c[t][1] * s_as[col + 1];
        float sd0 = c[t][0] * s_ad[col] + c[t][1] * s_ad[col + 1];
        float sa1 = c[t][2] * s_as[col] + c[t][3] * s_as[col + 1];
        float sd1 = c[t][2] * s_ad[col] + c[t][3] * s_ad[col + 1];
#pragma unroll
        for (int off = 1; off < 4; off <<= 1) {
            sa0 += __shfl_xor_sync(~0u, sa0, off);
            sd0 += __shfl_xor_sync(~0u, sd0, off);
            sa1 += __shfl_xor_sync(~0u, sa1, off);
            sd1 += __shfl_xor_sync(~0u, sd1, off);
        }
        al0[t] = sa0; ar0[t] = sd0; al1[t] = sa1; ar1[t] = sd1;
    }
    if ((l & 3) == 0) {
#pragma unroll
        for (int t = 0; t < 8; t++) {
            if (ok0) { g_al1[row0 * H1 + t] = al0[t]; g_ar1[row0 * H1 + t] = ar0[t]; }
            if (ok1) { g_al1[row1 * H1 + t] = al1[t]; g_ar1[row1 * H1 + t] = ar1[t]; }
        }
    }
}

// layer-1 aggregation + FUSED layer-2 node prep; accumulate loop unrolled x4 (MLP)
__global__ void agg1_kernel(const float* __restrict__ b1, const float* __restrict__ W2,
                            const float* __restrict__ as2, const float* __restrict__ ad2) {
    __shared__ float s_ex[8][256];
    int gw = (blockIdx.x * blockDim.x + threadIdx.x) >> 5;
    int w  = (threadIdx.x >> 5);
    int lane = threadIdx.x & 31;
    if (gw >= NN) return;
    int d = gw;
    int beg = g_off[d], end = g_off[d + 1];
    float4 ar0 = *(const float4*)&g_ar1[d * H1];
    float4 ar1 = *(const float4*)&g_ar1[d * H1 + 4];
    float dsum[8];
#pragma unroll
    for (int h = 0; h < 8; h++) dsum[h] = 0.f;
    float accx = 0.f, accy = 0.f;
    int hsel = lane >> 2;
    const float* h1c = g_h1 + 2 * lane;

    for (int b = beg; b < end; b += 32) {
        int n = min(32, end - b);
        int s_my = (lane < n) ? g_esrc[b + lane] : 0;
        if (lane < n) {
            float4 a0 = *(const float4*)&g_al1[s_my * H1];
            float4 a1 = *(const float4*)&g_al1[s_my * H1 + 4];
            float ex0 = fast_exp(lrelu(a0.x + ar0.x));
            float ex1 = fast_exp(lrelu(a0.y + ar0.y));
            float ex2 = fast_exp(lrelu(a0.z + ar0.z));
            float ex3 = fast_exp(lrelu(a0.w + ar0.w));
            float ex4 = fast_exp(lrelu(a1.x + ar1.x));
            float ex5 = fast_exp(lrelu(a1.y + ar1.y));
            float ex6 = fast_exp(lrelu(a1.z + ar1.z));
            float ex7 = fast_exp(lrelu(a1.w + ar1.w));
            dsum[0] += ex0; dsum[1] += ex1; dsum[2] += ex2; dsum[3] += ex3;
            dsum[4] += ex4; dsum[5] += ex5; dsum[6] += ex6; dsum[7] += ex7;
            *(float4*)&s_ex[w][lane * 8]     = make_float4(ex0, ex1, ex2, ex3);
            *(float4*)&s_ex[w][lane * 8 + 4] = make_float4(ex4, ex5, ex6, ex7);
        }
        __syncwarp();
        int j = 0;
        for (; j + 4 <= n; j += 4) {           // 4-way MLP
            int s0 = __shfl_sync(~0u, s_my, j);
            int s1 = __shfl_sync(~0u, s_my, j + 1);
            int s2 = __shfl_sync(~0u, s_my, j + 2);
            int s3 = __shfl_sync(~0u, s_my, j + 3);
            float2 h0 = *(const float2*)(h1c + (size_t)s0 * D1);
            float2 h1v = *(const float2*)(h1c + (size_t)s1 * D1);
            float2 h2 = *(const float2*)(h1c + (size_t)s2 * D1);
            float2 h3 = *(const float2*)(h1c + (size_t)s3 * D1);
            float e0 = s_ex[w][(j)     * 8 + hsel];
            float e1 = s_ex[w][(j + 1) * 8 + hsel];
            float e2 = s_ex[w][(j + 2) * 8 + hsel];
            float e3 = s_ex[w][(j + 3) * 8 + hsel];
            accx = fmaf(h0.x, e0, accx); accy = fmaf(h0.y, e0, accy);
            accx = fmaf(h1v.x, e1, accx); accy = fmaf(h1v.y, e1, accy);
            accx = fmaf(h2.x, e2, accx); accy = fmaf(h2.y, e2, accy);
            accx = fmaf(h3.x, e3, accx); accy = fmaf(h3.y, e3, accy);
        }
        for (; j < n; j++) {
            int s = __shfl_sync(~0u, s_my, j);
            float exv = s_ex[w][j * 8 + hsel];
            float2 hv = *(const float2*)(h1c + (size_t)s * D1);
            accx = fmaf(hv.x, exv, accx);
            accy = fmaf(hv.y, exv, accy);
        }
        __syncwarp();
    }
#pragma unroll
    for (int h = 0; h < 8; h++) {
#pragma unroll
        for (int off = 16; off; off >>= 1)
            dsum[h] += __shfl_xor_sync(~0u, dsum[h], off);
    }
    float rc = 1.f / (dsum[hsel] + 1e-16f);
    float2 bb = *(const float2*)&b1[2 * lane];
    float h2x = elu1(fmaf(accx, rc, bb.x));
    float h2y = elu1(fmaf(accy, rc, bb.y));
    float p[C2];
#pragma unroll
    for (int c = 0; c < C2; c++)
        p[c] = fmaf(h2x, __ldg(&W2[(2 * lane) * C2 + c]),
               h2y * __ldg(&W2[(2 * lane + 1) * C2 + c]));
#pragma unroll
    for (int off = 16; off; off >>= 1)
#pragma unroll
        for (int c = 0; c < C2; c++) p[c] += __shfl_xor_sync(~0u, p[c], off);
    float al = 0.f, ar = 0.f;
#pragma unroll
    for (int c = 0; c < C2; c++) {
        al = fmaf(p[c], __ldg(&as2[c]), al);
        ar = fmaf(p[c], __ldg(&ad2[c]), ar);
    }
    if (lane == 0) { g_al2[d] = al; g_ar2[d] = ar; }
    if (lane < C2) {
        float v = p[0];
#pragma unroll
        for (int c = 1; c < C2; c++) if (lane == c) v = p[c];
        g_z2[d * C2 + lane] = v;
    }
}

// layer-2 aggregation + fused log_softmax; accumulate loop unrolled x4
__global__ void agg2_kernel(const float* __restrict__ b2, float* __restrict__ out) {
    int d = (blockIdx.x * blockDim.x + threadIdx.x) >> 5;
    int lane = threadIdx.x & 31;
    if (d >= NN) return;
    int beg = g_off[d], end = g_off[d + 1];
    float ard = g_ar2[d];
    float acc = 0.f, dsum = 0.f;
    bool cl = lane < C2;
    for (int b = beg; b < end; b += 32) {
        int n = min(32, end - b);
        int s_my = (b + lane < end) ? g_esrc[b + lane] : 0;
        float ex_my = (b + lane < end) ? fast_exp(lrelu(g_al2[s_my] + ard)) : 0.f;
        dsum += ex_my;
        int j = 0;
        for (; j + 4 <= n; j += 4) {
            int s0 = __shfl_sync(~0u, s_my, j);
            int s1 = __shfl_sync(~0u, s_my, j + 1);
            int s2 = __shfl_sync(~0u, s_my, j + 2);
            int s3 = __shfl_sync(~0u, s_my, j + 3);
            float e0 = __shfl_sync(~0u, ex_my, j);
            float e1 = __shfl_sync(~0u, ex_my, j + 1);
            float e2 = __shfl_sync(~0u, ex_my, j + 2);
            float e3 = __shfl_sync(~0u, ex_my, j + 3);
            float z0 = cl ? g_z2[s0 * C2 + lane] : 0.f;
            float z1 = cl ? g_z2[s1 * C2 + lane] : 0.f;
            float z2 = cl ? g_z2[s2 * C2 + lane] : 0.f;
            float z3 = cl ? g_z2[s3 * C2 + lane] : 0.f;
            acc = fmaf(z0, e0, acc);
            acc = fmaf(z1, e1, acc);
            acc = fmaf(z2, e2, acc);
            acc = fmaf(z3, e3, acc);
        }
        for (; j < n; j++) {
            int   s  = __shfl_sync(~0u, s_my, j);
            float ex = __shfl_sync(~0u, ex_my, j);
            if (cl) acc = fmaf(g_z2[s * C2 + lane], ex, acc);
        }
    }
#pragma unroll
    for (int off = 16; off; off >>= 1)
        dsum += __shfl_xor_sync(~0u, dsum, off);
    float rc = 1.f / (dsum + 1e-16f);
    float v = cl ? fmaf(acc, rc, __ldg(&b2[lane])) : -1e30f;
    float m = v;
#pragma unroll
    for (int off = 8; off; off >>= 1)
        m = fmaxf(m, __shfl_xor_sync(~0u, m, off, 16));
    float s = cl ? fast_exp(v - m) : 0.f;
#pragma unroll
    for (int off = 8; off; off >>= 1)
        s += __shfl_xor_sync(~0u, s, off, 16);
    float l = m + logf(s);
    if (cl) out[(size_t)d * C2 + lane] = v - l;
}

// ---------------- launch ----------------
extern "C" void kernel_launch(void* const* d_in, const int* in_sizes, int n_in,
                              void* d_out, int out_size) {
    const float* x   = (const float*)d_in[0];
    const int*   ei  = (const int*)d_in[1];    // int32 (JAX x64 disabled)
    const float* W1  = (const float*)d_in[2];
    const float* as1 = (const float*)d_in[3];
    const float* ad1 = (const float*)d_in[4];
    const float* b1  = (const float*)d_in[5];
    const float* W2  = (const float*)d_in[6];
    const float* as2 = (const float*)d_in[7];
    const float* ad2 = (const float*)d_in[8];
    const float* b2  = (const float*)d_in[9];

    int E = in_sizes[1] / 2;
    const int* src = ei;
    const int* dst = ei + E;
    int tot = E + NN;
    int nb1 = (NN + 1023) / 1024;

    bprep_kernel  <<<32, 256>>>(W1);                                    // 0
    hist_kernel   <<<(tot + 255) / 256, 256>>>(src, dst, E);            // 1
    scan1_kernel  <<<nb1, 1024>>>();                                    // 2
    gemm1_kernel  <<<(NN + 127) / 128, 256>>>(x, as1, ad1);             // 3 <- profiled
    scan2_kernel  <<<1, 128>>>(nb1);                                    // 4
    scan3_kernel  <<<nb1, 1024>>>();                                    // 5
    scatter_kernel<<<(tot + 255) / 256, 256>>>(src, dst, E);            // 6
    agg1_kernel   <<<(NN * 32 + 255) / 256, 256>>>(b1, W2, as2, ad2);   // 7
    agg2_kernel   <<<(NN * 32 + 255) / 256, 256>>>(b2, (float*)d_out);  // 8
}

// round 12
// speedup vs baseline: 2.4126x; 1.0144x over previous
#include <cuda_runtime.h>
#include <cuda_bf16.h>
#include <cstdint>

#define NN   100000
#define FIN  512
#define H1   8
#define D1   64      // H1*C1
#define C2   10
#define EMAXSZ 1700000
#define KSTEPS 32    // 512 / 16

// ---------------- scratch (no allocs allowed) ----------------
__device__ float g_h1 [NN * D1];     // layer1 features   25.6 MB
__device__ float g_al1[NN * H1];
__device__ float g_ar1[NN * H1];
__device__ float g_z2 [NN * C2];
__device__ float g_al2[NN];
__device__ float g_ar2[NN];
// B fragments (bf16 hi/lo) in mma layout: [(ks*8+t)*64 + 2*lane + {0,1}]
__device__ uint32_t g_bh[KSTEPS * 8 * 64];
__device__ uint32_t g_bl[KSTEPS * 8 * 64];
// sorted-by-dst edge structures
__device__ int   g_cnt [NN];         // zero at entry (module init; scan3 restores)
__device__ int   g_tmp [NN];
__device__ int   g_bsum[128];
__device__ int   g_bsum2[128];
__device__ int   g_off [NN + 1];
__device__ int   g_pos [NN];
__device__ int   g_esrc[EMAXSZ];

// ---------------- helpers ----------------
__device__ __forceinline__ float lrelu(float x) { return x > 0.f ? x : 0.2f * x; }

__device__ __forceinline__ float fast_exp(float x) {
    float t = x * 1.4426950408889634f;
    t = fminf(fmaxf(t, -126.f), 126.f);
    float fi = floorf(t);
    float f  = t - fi;
    int   i  = (int)fi;
    float p = 1.5403530e-4f;
    p = fmaf(p, f, 1.3333558e-3f);
    p = fmaf(p, f, 9.6181291e-3f);
    p = fmaf(p, f, 5.5504109e-2f);
    p = fmaf(p, f, 2.4022651e-1f);
    p = fmaf(p, f, 6.9314718e-1f);
    p = fmaf(p, f, 1.0f);
    return __uint_as_float(__float_as_uint(p) + ((unsigned)i << 23));
}

__device__ __forceinline__ float elu1(float x) {
    return x > 0.f ? x : fast_exp(fmaxf(x, -80.f)) - 1.f;
}

__device__ __forceinline__ uint32_t pkbf2(float a, float b) {
    __nv_bfloat162 t = __floats2bfloat162_rn(a, b);
    return *(uint32_t*)&t;
}
__device__ __forceinline__ float bf2f(float v) {
    return __bfloat162float(__float2bfloat16_rn(v));
}

// m16n8k16 row.col bf16 -> f32 accum
__device__ __forceinline__ void mma16816(float* c, const uint32_t* a,
                                         uint32_t b0, uint32_t b1) {
    asm volatile(
        "mma.sync.aligned.m16n8k16.row.col.f32.bf16.bf16.f32 "
        "{%0,%1,%2,%3}, {%4,%5,%6,%7}, {%8,%9}, {%0,%1,%2,%3};"
        : "+f"(c[0]), "+f"(c[1]), "+f"(c[2]), "+f"(c[3])
        : "r"(a[0]), "r"(a[1]), "r"(a[2]), "r"(a[3]), "r"(b0), "r"(b1));
}

// ---------------- B fragment precompute ----------------
__global__ void bprep_kernel(const float* __restrict__ W) {
    int id = blockIdx.x * blockDim.x + threadIdx.x;   // 8192 threads
    if (id >= KSTEPS * 8 * 32) return;
    int l  = id & 31;
    int t  = (id >> 5) & 7;
    int ks = id >> 8;
    int k0 = ks * 16, n0 = t * 8;
    int n  = n0 + (l >> 2);
    int ka = k0 + 2 * (l & 3);
    float w00 = W[(ka)     * D1 + n], w01 = W[(ka + 1) * D1 + n];
    float w08 = W[(ka + 8) * D1 + n], w09 = W[(ka + 9) * D1 + n];
    float h00 = bf2f(w00), h01 = bf2f(w01), h08 = bf2f(w08), h09 = bf2f(w09);
    int idx = (ks * 8 + t) * 64 + 2 * l;
    g_bh[idx]     = pkbf2(w00, w01);
    g_bh[idx + 1] = pkbf2(w08, w09);
    g_bl[idx]     = pkbf2(w00 - h00, w01 - h01);
    g_bl[idx + 1] = pkbf2(w08 - h08, w09 - h09);
}

// ---------------- sort pipeline (launch-ordered, no spin-waits) ----------------
__device__ __forceinline__ bool edge_sd(const int* __restrict__ src,
                                        const int* __restrict__ dst,
                                        int e, int E, int& s, int& d) {
    if (e < E) { s = src[e]; d = dst[e]; }
    else       { s = d = e - E; }
    return (unsigned)s < NN && (unsigned)d < NN;
}

__global__ void hist_kernel(const int* __restrict__ src,
                            const int* __restrict__ dst, int E) {
    int e = blockIdx.x * blockDim.x + threadIdx.x;
    if (e >= E + NN) return;
    int s, d;
    if (!edge_sd(src, dst, e, E, s, d)) return;
    atomicAdd(&g_cnt[d], 1);
}

__global__ void scan1_kernel() {
    __shared__ int sm[1024];
    int tid = threadIdx.x, i = blockIdx.x * 1024 + tid;
    int v = (i < NN) ? g_cnt[i] : 0;
    sm[tid] = v;
    __syncthreads();
#pragma unroll
    for (int off = 1; off < 1024; off <<= 1) {
        int t = (tid >= off) ? sm[tid - off] : 0;
        __syncthreads();
        sm[tid] += t;
        __syncthreads();
    }
    if (i < NN) g_tmp[i] = sm[tid];
    if (tid == 1023) g_bsum[blockIdx.x] = sm[1023];
}

__global__ void scan2_kernel(int nb) {
    __shared__ int sm[128];
    int tid = threadIdx.x;
    int v = (tid < nb) ? g_bsum[tid] : 0;
    sm[tid] = v;
    __syncthreads();
#pragma unroll
    for (int off = 1; off < 128; off <<= 1) {
        int t = (tid >= off) ? sm[tid - off] : 0;
        __syncthreads();
        sm[tid] += t;
        __syncthreads();
    }
    if (tid < nb) g_bsum2[tid] = sm[tid] - v;   // exclusive
}

__global__ void scan3_kernel() {
    int i = blockIdx.x * 1024 + threadIdx.x;
    if (i < NN) {
        int c    = g_cnt[i];
        int incl = g_tmp[i] + g_bsum2[blockIdx.x];
        g_off[i + 1] = incl;
        g_pos[i]     = incl - c;
        g_cnt[i]     = 0;
        if (i == 0) g_off[0] = 0;
    }
}

__global__ void scatter_kernel(const int* __restrict__ src,
                               const int* __restrict__ dst, int E) {
    int e = blockIdx.x * blockDim.x + threadIdx.x;
    if (e >= E + NN) return;
    int s, d;
    if (!edge_sd(src, dst, e, E, s, d)) return;
    int p = atomicAdd(&g_pos[d], 1);
    g_esrc[p] = s;
}

// ---------------- tensor-core GEMM (split-bf16 mma.sync, x-prefetch pipeline) ----------------
__global__ void __launch_bounds__(256, 2)
gemm1_kernel(const float* __restrict__ x,
             const float* __restrict__ a_src, const float* __restrict__ a_dst) {
    __shared__ float s_as[64], s_ad[64];
    int tid = threadIdx.x, w = tid >> 5, l = tid & 31;
    if (tid < 64) { s_as[tid] = a_src[tid]; s_ad[tid] = a_dst[tid]; }
    __syncthreads();

    int m0   = blockIdx.x * 128 + w * 16;
    int row0 = m0 + (l >> 2);
    int row1 = row0 + 8;
    const float* xr0 = x + (size_t)(row0 < NN ? row0 : 0) * FIN + 2 * (l & 3);
    const float* xr1 = x + (size_t)(row1 < NN ? row1 : 0) * FIN + 2 * (l & 3);

    float c[8][4];
#pragma unroll
    for (int t = 0; t < 8; t++)
#pragma unroll
        for (int q = 0; q < 4; q++) c[t][q] = 0.f;

    // prefetch pipeline: p* holds iteration ks's x values, loaded one iter ahead
    float2 p0 = *(const float2*)(xr0);
    float2 p1 = *(const float2*)(xr1);
    float2 p2 = *(const float2*)(xr0 + 8);
    float2 p3 = *(const float2*)(xr1 + 8);

    for (int ks = 0; ks < KSTEPS; ks++) {
        float2 v0 = p0, v1 = p1, v2 = p2, v3 = p3;
        if (ks + 1 < KSTEPS) {
            int k1 = (ks + 1) * 16;
            p0 = *(const float2*)(xr0 + k1);
            p1 = *(const float2*)(xr1 + k1);
            p2 = *(const float2*)(xr0 + k1 + 8);
            p3 = *(const float2*)(xr1 + k1 + 8);
        }
        float h0x = bf2f(v0.x), h0y = bf2f(v0.y);
        float h1x = bf2f(v1.x), h1y = bf2f(v1.y);
        float h2x = bf2f(v2.x), h2y = bf2f(v2.y);
        float h3x = bf2f(v3.x), h3y = bf2f(v3.y);
        uint32_t ah[4] = { pkbf2(h0x, h0y), pkbf2(h1x, h1y),
                           pkbf2(h2x, h2y), pkbf2(h3x, h3y) };
        uint32_t al[4] = { pkbf2(v0.x - h0x, v0.y - h0y),
                           pkbf2(v1.x - h1x, v1.y - h1y),
                           pkbf2(v2.x - h2x, v2.y - h2y),
                           pkbf2(v3.x - h3x, v3.y - h3y) };
        const uint2* bh = (const uint2*)(g_bh + ks * 8 * 64) + l;
        const uint2* bl = (const uint2*)(g_bl + ks * 8 * 64) + l;
#pragma unroll
        for (int t = 0; t < 8; t++) {
            uint2 b_hi = bh[t * 32];
            uint2 b_lo = bl[t * 32];
            mma16816(c[t], ah, b_hi.x, b_hi.y);
            mma16816(c[t], ah, b_lo.x, b_lo.y);
            mma16816(c[t], al, b_hi.x, b_hi.y);
        }
    }

    // epilogue: stream stores per tile (no long-lived arrays -> lower reg pressure)
    bool ok0 = row0 < NN, ok1 = row1 < NN;
    bool w0  = (l & 3) == 0;
#pragma unroll
    for (int t = 0; t < 8; t++) {
        int col = t * 8 + 2 * (l & 3);
        if (ok0) *(float2*)&g_h1[(size_t)row0 * D1 + col] = make_float2(c[t][0], c[t][1]);
        if (ok1) *(float2*)&g_h1[(size_t)row1 * D1 + col] = make_float2(c[t][2], c[t][3]);
        float sa0 = c[t][0] * s_as[col] + c[t][1] * s_as[col + 1];
        float sd0 = c[t][0] * s_ad[col] + c[t][1] * s_ad[col + 1];
        float sa1 = c[t][2] * s_as[col] + c[t][3] * s_as[col + 1];
        float sd1 = c[t][2] * s_ad[col] + c[t][3] * s_ad[col + 1];
#pragma unroll
        for (int off = 1; off < 4; off <<= 1) {
            sa0 += __shfl_xor_sync(~0u, sa0, off);
            sd0 += __shfl_xor_sync(~0u, sd0, off);
            sa1 += __shfl_xor_sync(~0u, sa1, off);
            sd1 += __shfl_xor_sync(~0u, sd1, off);
        }
        if (w0 && ok0) { g_al1[row0 * H1 + t] = sa0; g_ar1[row0 * H1 + t] = sd0; }
        if (w0 && ok1) { g_al1[row1 * H1 + t] = sa1; g_ar1[row1 * H1 + t] = sd1; }
    }
}

// layer-1 aggregation + FUSED layer-2 node prep; accumulate loop unrolled x4 (MLP)
__global__ void agg1_kernel(const float* __restrict__ b1, const float* __restrict__ W2,
                            const float* __restrict__ as2, const float* __restrict__ ad2) {
    __shared__ float s_ex[8][256];
    int gw = (blockIdx.x * blockDim.x + threadIdx.x) >> 5;
    int w  = (threadIdx.x >> 5);
    int lane = threadIdx.x & 31;
    if (gw >= NN) return;
    int d = gw;
    int beg = g_off[d], end = g_off[d + 1];
    float4 ar0 = *(const float4*)&g_ar1[d * H1];
    float4 ar1 = *(const float4*)&g_ar1[d * H1 + 4];
    float dsum[8];
#pragma unroll
    for (int h = 0; h < 8; h++) dsum[h] = 0.f;
    float accx = 0.f, accy = 0.f;
    int hsel = lane >> 2;
    const float* h1c = g_h1 + 2 * lane;

    for (int b = beg; b < end; b += 32) {
        int n = min(32, end - b);
        int s_my = (lane < n) ? g_esrc[b + lane] : 0;
        if (lane < n) {
            float4 a0 = *(const float4*)&g_al1[s_my * H1];
            float4 a1 = *(const float4*)&g_al1[s_my * H1 + 4];
            float ex0 = fast_exp(lrelu(a0.x + ar0.x));
            float ex1 = fast_exp(lrelu(a0.y + ar0.y));
            float ex2 = fast_exp(lrelu(a0.z + ar0.z));
            float ex3 = fast_exp(lrelu(a0.w + ar0.w));
            float ex4 = fast_exp(lrelu(a1.x + ar1.x));
            float ex5 = fast_exp(lrelu(a1.y + ar1.y));
            float ex6 = fast_exp(lrelu(a1.z + ar1.z));
            float ex7 = fast_exp(lrelu(a1.w + ar1.w));
            dsum[0] += ex0; dsum[1] += ex1; dsum[2] += ex2; dsum[3] += ex3;
            dsum[4] += ex4; dsum[5] += ex5; dsum[6] += ex6; dsum[7] += ex7;
            *(float4*)&s_ex[w][lane * 8]     = make_float4(ex0, ex1, ex2, ex3);
            *(float4*)&s_ex[w][lane * 8 + 4] = make_float4(ex4, ex5, ex6, ex7);
        }
        __syncwarp();
        int j = 0;
        for (; j + 4 <= n; j += 4) {           // 4-way MLP
            int s0 = __shfl_sync(~0u, s_my, j);
            int s1 = __shfl_sync(~0u, s_my, j + 1);
            int s2 = __shfl_sync(~0u, s_my, j + 2);
            int s3 = __shfl_sync(~0u, s_my, j + 3);
            float2 h0 = *(const float2*)(h1c + (size_t)s0 * D1);
            float2 h1v = *(const float2*)(h1c + (size_t)s1 * D1);
            float2 h2 = *(const float2*)(h1c + (size_t)s2 * D1);
            float2 h3 = *(const float2*)(h1c + (size_t)s3 * D1);
            float e0 = s_ex[w][(j)     * 8 + hsel];
            float e1 = s_ex[w][(j + 1) * 8 + hsel];
            float e2 = s_ex[w][(j + 2) * 8 + hsel];
            float e3 = s_ex[w][(j + 3) * 8 + hsel];
            accx = fmaf(h0.x, e0, accx); accy = fmaf(h0.y, e0, accy);
            accx = fmaf(h1v.x, e1, accx); accy = fmaf(h1v.y, e1, accy);
            accx = fmaf(h2.x, e2, accx); accy = fmaf(h2.y, e2, accy);
            accx = fmaf(h3.x, e3, accx); accy = fmaf(h3.y, e3, accy);
        }
        for (; j < n; j++) {
            int s = __shfl_sync(~0u, s_my, j);
            float exv = s_ex[w][j * 8 + hsel];
            float2 hv = *(const float2*)(h1c + (size_t)s * D1);
            accx = fmaf(hv.x, exv, accx);
            accy = fmaf(hv.y, exv, accy);
        }
        __syncwarp();
    }
#pragma unroll
    for (int h = 0; h < 8; h++) {
#pragma unroll
        for (int off = 16; off; off >>= 1)
            dsum[h] += __shfl_xor_sync(~0u, dsum[h], off);
    }
    float rc = 1.f / (dsum[hsel] + 1e-16f);
    float2 bb = *(const float2*)&b1[2 * lane];
    float h2x = elu1(fmaf(accx, rc, bb.x));
    float h2y = elu1(fmaf(accy, rc, bb.y));
    float p[C2];
#pragma unroll
    for (int c = 0; c < C2; c++)
        p[c] = fmaf(h2x, __ldg(&W2[(2 * lane) * C2 + c]),
               h2y * __ldg(&W2[(2 * lane + 1) * C2 + c]));
#pragma unroll
    for (int off = 16; off; off >>= 1)
#pragma unroll
        for (int c = 0; c < C2; c++) p[c] += __shfl_xor_sync(~0u, p[c], off);
    float al = 0.f, ar = 0.f;
#pragma unroll
    for (int c = 0; c < C2; c++) {
        al = fmaf(p[c], __ldg(&as2[c]), al);
        ar = fmaf(p[c], __ldg(&ad2[c]), ar);
    }
    if (lane == 0) { g_al2[d] = al; g_ar2[d] = ar; }
    if (lane < C2) {
        float v = p[0];
#pragma unroll
        for (int c = 1; c < C2; c++) if (lane == c) v = p[c];
        g_z2[d * C2 + lane] = v;
    }
}

// layer-2 aggregation + fused log_softmax; accumulate loop unrolled x4
__global__ void agg2_kernel(const float* __restrict__ b2, float* __restrict__ out) {
    int d = (blockIdx.x * blockDim.x + threadIdx.x) >> 5;
    int lane = threadIdx.x & 31;
    if (d >= NN) return;
    int beg = g_off[d], end = g_off[d + 1];
    float ard = g_ar2[d];
    float acc = 0.f, dsum = 0.f;
    bool cl = lane < C2;
    for (int b = beg; b < end; b += 32) {
        int n = min(32, end - b);
        int s_my = (b + lane < end) ? g_esrc[b + lane] : 0;
        float ex_my = (b + lane < end) ? fast_exp(lrelu(g_al2[s_my] + ard)) : 0.f;
        dsum += ex_my;
        int j = 0;
        for (; j + 4 <= n; j += 4) {
            int s0 = __shfl_sync(~0u, s_my, j);
            int s1 = __shfl_sync(~0u, s_my, j + 1);
            int s2 = __shfl_sync(~0u, s_my, j + 2);
            int s3 = __shfl_sync(~0u, s_my, j + 3);
            float e0 = __shfl_sync(~0u, ex_my, j);
            float e1 = __shfl_sync(~0u, ex_my, j + 1);
            float e2 = __shfl_sync(~0u, ex_my, j + 2);
            float e3 = __shfl_sync(~0u, ex_my, j + 3);
            float z0 = cl ? g_z2[s0 * C2 + lane] : 0.f;
            float z1 = cl ? g_z2[s1 * C2 + lane] : 0.f;
            float z2 = cl ? g_z2[s2 * C2 + lane] : 0.f;
            float z3 = cl ? g_z2[s3 * C2 + lane] : 0.f;
            acc = fmaf(z0, e0, acc);
            acc = fmaf(z1, e1, acc);
            acc = fmaf(z2, e2, acc);
            acc = fmaf(z3, e3, acc);
        }
        for (; j < n; j++) {
            int   s  = __shfl_sync(~0u, s_my, j);
            float ex = __shfl_sync(~0u, ex_my, j);
            if (cl) acc = fmaf(g_z2[s * C2 + lane], ex, acc);
        }
    }
#pragma unroll
    for (int off = 16; off; off >>= 1)
        dsum += __shfl_xor_sync(~0u, dsum, off);
    float rc = 1.f / (dsum + 1e-16f);
    float v = cl ? fmaf(acc, rc, __ldg(&b2[lane])) : -1e30f;
    float m = v;
#pragma unroll
    for (int off = 8; off; off >>= 1)
        m = fmaxf(m, __shfl_xor_sync(~0u, m, off, 16));
    float s = cl ? fast_exp(v - m) : 0.f;
#pragma unroll
    for (int off = 8; off; off >>= 1)
        s += __shfl_xor_sync(~0u, s, off, 16);
    float l = m + logf(s);
    if (cl) out[(size_t)d * C2 + lane] = v - l;
}

// ---------------- launch ----------------
extern "C" void kernel_launch(void* const* d_in, const int* in_sizes, int n_in,
                              void* d_out, int out_size) {
    const float* x   = (const float*)d_in[0];
    const int*   ei  = (const int*)d_in[1];    // int32 (JAX x64 disabled)
    const float* W1  = (const float*)d_in[2];
    const float* as1 = (const float*)d_in[3];
    const float* ad1 = (const float*)d_in[4];
    const float* b1  = (const float*)d_in[5];
    const float* W2  = (const float*)d_in[6];
    const float* as2 = (const float*)d_in[7];
    const float* ad2 = (const float*)d_in[8];
    const float* b2  = (const float*)d_in[9];

    int E = in_sizes[1] / 2;
    const int* src = ei;
    const int* dst = ei + E;
    int tot = E + NN;
    int nb1 = (NN + 1023) / 1024;

    bprep_kernel  <<<32, 256>>>(W1);                                    // 0
    hist_kernel   <<<(tot + 255) / 256, 256>>>(src, dst, E);            // 1
    scan1_kernel  <<<nb1, 1024>>>();                                    // 2
    gemm1_kernel  <<<(NN + 127) / 128, 256>>>(x, as1, ad1);             // 3 <- profiled
    scan2_kernel  <<<1, 128>>>(nb1);                                    // 4
    scan3_kernel  <<<nb1, 1024>>>();                                    // 5
    scatter_kernel<<<(tot + 255) / 256, 256>>>(src, dst, E);            // 6
    agg1_kernel   <<<(NN * 32 + 255) / 256, 256>>>(b1, W2, as2, ad2);   // 7
    agg2_kernel   <<<(NN * 32 + 255) / 256, 256>>>(b2, (float*)d_out);  // 8
}